// round 1
// baseline (speedup 1.0000x reference)
#include <cuda_runtime.h>
#include <math.h>

// Problem constants
constexpr int B_ = 4;
constexpr int T_ = 2048;
constexpr int D_ = 1024;
constexpr int H_ = 16;
constexpr int DK_ = 64;
constexpr int M_ = B_ * T_;   // 8192
constexpr int N_ = D_;        // 1024
constexpr int K_ = D_;        // 1024

// Scratch (device globals: allocation-free per harness rules)
__device__ float g_q[(size_t)B_ * H_ * T_ * DK_];     // [B,H,T,DK]
__device__ float g_k[(size_t)B_ * H_ * T_ * DK_];
__device__ float g_v[(size_t)B_ * H_ * T_ * DK_];
__device__ float g_attn[(size_t)B_ * T_ * D_];        // [B,T,D]

// ---------------------------------------------------------------------------
// GEMM: C = A @ W^T + bias.  A:[M,K] row-major, W:[N,K] row-major (Linear).
// MODE 0/1/2: write into g_q/g_k/g_v with [B,H,T,DK] layout.
// MODE 3:     A is g_attn, write plain row-major into C (d_out).
// 128x128 block tile, BK=8, 256 threads, 8x8 per thread.
// ---------------------------------------------------------------------------
template<int MODE>
__global__ __launch_bounds__(256, 2)
void gemm_kernel(const float* __restrict__ A, const float* __restrict__ W,
                 const float* __restrict__ bias, float* __restrict__ C)
{
    __shared__ float As[8][128];
    __shared__ float Ws[8][128];

    const float* Ain = (MODE == 3) ? (const float*)g_attn : A;

    const int tid = threadIdx.x;
    const int tx = tid & 15;
    const int ty = tid >> 4;
    const int bm = blockIdx.y * 128;
    const int bn = blockIdx.x * 128;

    const int lrow = tid >> 1;        // 0..127
    const int lk = (tid & 1) * 4;     // 0 or 4

    const float* Ap = Ain + (size_t)(bm + lrow) * K_ + lk;
    const float* Wp = W + (size_t)(bn + lrow) * K_ + lk;

    float acc[8][8];
#pragma unroll
    for (int i = 0; i < 8; ++i)
#pragma unroll
        for (int j = 0; j < 8; ++j) acc[i][j] = 0.0f;

    for (int k0 = 0; k0 < K_; k0 += 8) {
        float4 a4 = *(const float4*)(Ap + k0);
        float4 w4 = *(const float4*)(Wp + k0);
        As[lk + 0][lrow] = a4.x;
        As[lk + 1][lrow] = a4.y;
        As[lk + 2][lrow] = a4.z;
        As[lk + 3][lrow] = a4.w;
        Ws[lk + 0][lrow] = w4.x;
        Ws[lk + 1][lrow] = w4.y;
        Ws[lk + 2][lrow] = w4.z;
        Ws[lk + 3][lrow] = w4.w;
        __syncthreads();

#pragma unroll
        for (int kk = 0; kk < 8; ++kk) {
            float af[8], wf[8];
            *(float4*)&af[0] = *(const float4*)&As[kk][ty * 8 + 0];
            *(float4*)&af[4] = *(const float4*)&As[kk][ty * 8 + 4];
            *(float4*)&wf[0] = *(const float4*)&Ws[kk][tx * 8 + 0];
            *(float4*)&wf[4] = *(const float4*)&Ws[kk][tx * 8 + 4];
#pragma unroll
            for (int i = 0; i < 8; ++i)
#pragma unroll
                for (int j = 0; j < 8; ++j)
                    acc[i][j] = fmaf(af[i], wf[j], acc[i][j]);
        }
        __syncthreads();
    }

    float bb[8];
#pragma unroll
    for (int j = 0; j < 8; ++j) bb[j] = bias[bn + tx * 8 + j];

#pragma unroll
    for (int i = 0; i < 8; ++i) {
        const int row = bm + ty * 8 + i;
#pragma unroll
        for (int j = 0; j < 8; ++j) {
            const int col = bn + tx * 8 + j;
            const float cval = acc[i][j] + bb[j];
            if (MODE == 3) {
                C[(size_t)row * N_ + col] = cval;
            } else {
                const int b = row >> 11;          // row / T_
                const int t = row & (T_ - 1);
                const int h = col >> 6;           // col / DK_
                const int d = col & (DK_ - 1);
                float* dst = (MODE == 0) ? g_q : (MODE == 1) ? g_k : g_v;
                dst[(((size_t)b * H_ + h) * T_ + t) * DK_ + d] = cval;
            }
        }
    }
}

// ---------------------------------------------------------------------------
// Flash attention, fp32, causal. One block = 64 query rows of one (b,h).
// 256 threads, 4x4 register tile per thread on 64x64 score/output tiles.
// Ps (post-exp probabilities) aliases the K tile buffer (padded stride 68).
// ---------------------------------------------------------------------------
__global__ __launch_bounds__(256, 1)
void attn_kernel()
{
    extern __shared__ float sm[];
    float* Qs = sm;                          // 64*64
    float* KPs = Qs + 64 * 64;               // 64*68 (K tile, then P tile)
    float* Vs = KPs + 64 * 68;               // 64*64
    float* row_m = Vs + 64 * 64;              // 64
    float* row_l = row_m + 64;                // 64
    float* row_scale = row_l + 64;            // 64

    const int tid = threadIdx.x;
    const int tx = tid & 15;
    const int ty = tid >> 4;
    const int i0 = ty * 4;
    const int j0 = tx * 4;

    const int bh = blockIdx.y;      // 0..63
    const int qt = blockIdx.x;      // 0..31 (query tile)

    const float* Qg = g_q + (size_t)bh * T_ * DK_ + (size_t)qt * 64 * DK_;
    const float* Kg0 = g_k + (size_t)bh * T_ * DK_;
    const float* Vg0 = g_v + (size_t)bh * T_ * DK_;

    // Load Q tile
#pragma unroll
    for (int it = 0; it < 4; ++it) {
        const int idx = tid + it * 256;
        const int r = idx >> 4;
        const int c = (idx & 15) * 4;
        *(float4*)&Qs[r * 64 + c] = *(const float4*)(Qg + r * 64 + c);
    }
    if (tid < 64) { row_m[tid] = -1e30f; row_l[tid] = 0.0f; }

    float o[4][4];
#pragma unroll
    for (int i = 0; i < 4; ++i)
#pragma unroll
        for (int j = 0; j < 4; ++j) o[i][j] = 0.0f;

    __syncthreads();

    const float invs = 0.125f;   // 1/sqrt(64)

    for (int kt = 0; kt <= qt; ++kt) {
        const float* Kg = Kg0 + (size_t)kt * 64 * DK_;
        const float* Vg = Vg0 + (size_t)kt * 64 * DK_;
#pragma unroll
        for (int it = 0; it < 4; ++it) {
            const int idx = tid + it * 256;
            const int r = idx >> 4;
            const int c = (idx & 15) * 4;
            *(float4*)&KPs[r * 68 + c] = *(const float4*)(Kg + r * 64 + c);
            *(float4*)&Vs[r * 64 + c] = *(const float4*)(Vg + r * 64 + c);
        }
        __syncthreads();

        // S = Q @ K^T (4x4 per thread), vectorized over d
        float s[4][4];
#pragma unroll
        for (int i = 0; i < 4; ++i)
#pragma unroll
            for (int j = 0; j < 4; ++j) s[i][j] = 0.0f;

        for (int d = 0; d < 64; d += 4) {
            float qv[4][4], kv[4][4];
#pragma unroll
            for (int i = 0; i < 4; ++i) {
                float4 t4 = *(const float4*)&Qs[(i0 + i) * 64 + d];
                qv[i][0] = t4.x; qv[i][1] = t4.y; qv[i][2] = t4.z; qv[i][3] = t4.w;
            }
#pragma unroll
            for (int j = 0; j < 4; ++j) {
                float4 t4 = *(const float4*)&KPs[(j0 + j) * 68 + d];
                kv[j][0] = t4.x; kv[j][1] = t4.y; kv[j][2] = t4.z; kv[j][3] = t4.w;
            }
#pragma unroll
            for (int i = 0; i < 4; ++i)
#pragma unroll
                for (int j = 0; j < 4; ++j)
#pragma unroll
                    for (int c = 0; c < 4; ++c)
                        s[i][j] = fmaf(qv[i][c], kv[j][c], s[i][j]);
        }

        // scale + causal mask (only diagonal tile needs masking)
        if (kt == qt) {
#pragma unroll
            for (int i = 0; i < 4; ++i)
#pragma unroll
                for (int j = 0; j < 4; ++j)
                    s[i][j] = ((j0 + j) <= (i0 + i)) ? s[i][j] * invs : -1e30f;
        } else {
#pragma unroll
            for (int i = 0; i < 4; ++i)
#pragma unroll
                for (int j = 0; j < 4; ++j) s[i][j] *= invs;
        }

        __syncthreads();   // all K reads done before overwriting buffer as P

#pragma unroll
        for (int i = 0; i < 4; ++i)
#pragma unroll
            for (int j = 0; j < 4; ++j)
                KPs[(i0 + i) * 68 + (j0 + j)] = s[i][j];
        __syncthreads();

        // Online softmax per row (threads 0..63)
        if (tid < 64) {
            float* pr = &KPs[tid * 68];
            const float mo = row_m[tid];
            float mt = mo;
#pragma unroll 8
            for (int j = 0; j < 64; ++j) mt = fmaxf(mt, pr[j]);
            const float sc = __expf(mo - mt);
            float l = row_l[tid] * sc;
#pragma unroll 8
            for (int j = 0; j < 64; ++j) {
                const float p = __expf(pr[j] - mt);
                pr[j] = p;
                l += p;
            }
            row_m[tid] = mt;
            row_l[tid] = l;
            row_scale[tid] = sc;
        }
        __syncthreads();

        // Rescale running output, then O += P @ V
        float fac[4];
#pragma unroll
        for (int i = 0; i < 4; ++i) fac[i] = row_scale[i0 + i];
#pragma unroll
        for (int i = 0; i < 4; ++i)
#pragma unroll
            for (int j = 0; j < 4; ++j) o[i][j] *= fac[i];

        for (int k = 0; k < 64; k += 4) {
            float pv[4][4], vv[4][4];
#pragma unroll
            for (int i = 0; i < 4; ++i) {
                float4 t4 = *(const float4*)&KPs[(i0 + i) * 68 + k];
                pv[i][0] = t4.x; pv[i][1] = t4.y; pv[i][2] = t4.z; pv[i][3] = t4.w;
            }
#pragma unroll
            for (int c = 0; c < 4; ++c) {
                float4 t4 = *(const float4*)&Vs[(k + c) * 64 + j0];
                vv[c][0] = t4.x; vv[c][1] = t4.y; vv[c][2] = t4.z; vv[c][3] = t4.w;
            }
#pragma unroll
            for (int i = 0; i < 4; ++i)
#pragma unroll
                for (int j = 0; j < 4; ++j)
#pragma unroll
                    for (int c = 0; c < 4; ++c)
                        o[i][j] = fmaf(pv[i][c], vv[c][j], o[i][j]);
        }
        __syncthreads();   // before next tile overwrites KPs/Vs
    }

    // Normalize and write to [B,T,D] (heads concatenated)
    const int b = bh >> 4;
    const int h = bh & 15;
#pragma unroll
    for (int i = 0; i < 4; ++i) {
        const float inv = 1.0f / row_l[i0 + i];
        const int t = qt * 64 + i0 + i;
        float* outp = g_attn + ((size_t)b * T_ + t) * D_ + h * DK_ + j0;
#pragma unroll
        for (int j = 0; j < 4; ++j) outp[j] = o[i][j] * inv;
    }
}

// ---------------------------------------------------------------------------
// Launch
// ---------------------------------------------------------------------------
extern "C" void kernel_launch(void* const* d_in, const int* in_sizes, int n_in,
                              void* d_out, int out_size)
{
    (void)in_sizes; (void)n_in; (void)out_size;
    const float* x  = (const float*)d_in[0];
    // d_in[1] is the causal mask; causality applied analytically.
    const float* Wq = (const float*)d_in[2];
    const float* Wk = (const float*)d_in[3];
    const float* Wv = (const float*)d_in[4];
    const float* Wo = (const float*)d_in[5];
    const float* bq = (const float*)d_in[6];
    const float* bk = (const float*)d_in[7];
    const float* bv = (const float*)d_in[8];
    const float* bo = (const float*)d_in[9];
    float* out = (float*)d_out;

    dim3 ggrid(N_ / 128, M_ / 128);   // (8, 64)
    gemm_kernel<0><<<ggrid, 256>>>(x, Wq, bq, nullptr);
    gemm_kernel<1><<<ggrid, 256>>>(x, Wk, bk, nullptr);
    gemm_kernel<2><<<ggrid, 256>>>(x, Wv, bv, nullptr);

    const int smem_bytes = (64 * 64 + 64 * 68 + 64 * 64 + 3 * 64) * (int)sizeof(float);
    cudaFuncSetAttribute(attn_kernel, cudaFuncAttributeMaxDynamicSharedMemorySize, smem_bytes);
    attn_kernel<<<dim3(T_ / 64, B_ * H_), 256, smem_bytes>>>();

    gemm_kernel<3><<<ggrid, 256>>>(x /*unused*/, Wo, bo, out);
}

// round 2
// speedup vs baseline: 1.4896x; 1.4896x over previous
#include <cuda_runtime.h>
#include <cuda_bf16.h>
#include <math.h>
#include <stdint.h>

// Problem constants
constexpr int B_ = 4;
constexpr int T_ = 2048;
constexpr int D_ = 1024;
constexpr int H_ = 16;
constexpr int DK_ = 64;
constexpr int M_ = B_ * T_;   // 8192
constexpr int N_ = D_;        // 1024
constexpr int K_ = D_;        // 1024

// bf16 split arenas (hi + lo). Layout: [x (M*K)][W0..W3 (4*N*K)][attn (M*K)]
constexpr size_t XOFF = 0;
constexpr size_t WOFF = (size_t)M_ * K_;                    // 8388608
constexpr size_t AOFF = WOFF + 4ull * N_ * K_;              // +4194304
constexpr size_t ARENA = AOFF + (size_t)M_ * K_;

__device__ __nv_bfloat16 g_hi[ARENA];
__device__ __nv_bfloat16 g_lo[ARENA];

__device__ float g_q[(size_t)B_ * H_ * T_ * DK_];     // [B,H,T,DK]
__device__ float g_k[(size_t)B_ * H_ * T_ * DK_];
__device__ float g_v[(size_t)B_ * H_ * T_ * DK_];
__device__ float g_attn[(size_t)M_ * D_];             // [B,T,D]

// ---------------------------------------------------------------------------
// Split fp32 -> bf16 hi + bf16 lo (residual). hi+lo reproduces x to ~2^-18.
// ---------------------------------------------------------------------------
__global__ void split_kernel(const float* __restrict__ in, size_t dstOff, int n4)
{
    int i = blockIdx.x * blockDim.x + threadIdx.x;
    if (i >= n4) return;
    float4 v = ((const float4*)in)[i];
    float vv[4] = {v.x, v.y, v.z, v.w};
    __nv_bfloat16 h[4], l[4];
#pragma unroll
    for (int c = 0; c < 4; ++c) {
        h[c] = __float2bfloat16_rn(vv[c]);
        l[c] = __float2bfloat16_rn(vv[c] - __bfloat162float(h[c]));
    }
    __nv_bfloat162* ph = (__nv_bfloat162*)(g_hi + dstOff + (size_t)i * 4);
    __nv_bfloat162* pl = (__nv_bfloat162*)(g_lo + dstOff + (size_t)i * 4);
    ph[0] = __halves2bfloat162(h[0], h[1]);
    ph[1] = __halves2bfloat162(h[2], h[3]);
    pl[0] = __halves2bfloat162(l[0], l[1]);
    pl[1] = __halves2bfloat162(l[2], l[3]);
}

// ---------------------------------------------------------------------------
// MMA helpers
// ---------------------------------------------------------------------------
__device__ __forceinline__ void cp16(uint32_t dst, const void* src)
{
    asm volatile("cp.async.cg.shared.global [%0],[%1],16;\n" :: "r"(dst), "l"(src));
}

__device__ __forceinline__ void ldsm4(uint32_t* r, uint32_t addr)
{
    asm volatile("ldmatrix.sync.aligned.m8n8.x4.shared.b16 {%0,%1,%2,%3},[%4];"
                 : "=r"(r[0]), "=r"(r[1]), "=r"(r[2]), "=r"(r[3]) : "r"(addr));
}

__device__ __forceinline__ void mma16816(float* c, const uint32_t* a, const uint32_t* b)
{
    asm volatile(
        "mma.sync.aligned.m16n8k16.row.col.f32.bf16.bf16.f32 "
        "{%0,%1,%2,%3},{%4,%5,%6,%7},{%8,%9},{%0,%1,%2,%3};"
        : "+f"(c[0]), "+f"(c[1]), "+f"(c[2]), "+f"(c[3])
        : "r"(a[0]), "r"(a[1]), "r"(a[2]), "r"(a[3]), "r"(b[0]), "r"(b[1]));
}

// smem stage layout (bytes, bf16 tiles 128x32 padded to row stride 40 elems = 80B):
//   +0      A_hi   (10240 B)
//   +10240  A_lo
//   +20480  W_hi
//   +30720  W_lo
// stage stride = 40960 B, 2 stages = 81920 B dynamic smem
constexpr int STAGE_B = 40960;

__device__ __forceinline__ void stage_load(
    const __nv_bfloat16* Ah, const __nv_bfloat16* Al,
    const __nv_bfloat16* Wh, const __nv_bfloat16* Wl,
    uint32_t sb, int bm, int bn, int k0, int tid)
{
#pragma unroll
    for (int half = 0; half < 2; ++half) {
        int c = tid + half * 256;      // 0..511 chunk id
        int row = c >> 2;
        int cc = c & 3;
        uint32_t so = (uint32_t)(row * 80 + cc * 16);
        size_t ga = (size_t)(bm + row) * K_ + k0 + cc * 8;
        size_t gw = (size_t)(bn + row) * K_ + k0 + cc * 8;
        cp16(sb + so,         Ah + ga);
        cp16(sb + 10240 + so, Al + ga);
        cp16(sb + 20480 + so, Wh + gw);
        cp16(sb + 30720 + so, Wl + gw);
    }
    asm volatile("cp.async.commit_group;\n" ::);
}

// ---------------------------------------------------------------------------
// Tensor-core GEMM: C = A @ W^T + bias, error-compensated bf16 (3 MMAs).
// A:[M,K], W:[N,K]. 128x128 block tile, BK=32, 8 warps (4m x 2n),
// warp tile 32x64 = 2 m16 x 8 n8 mma tiles.
// MODE 0/1/2: scatter into g_q/g_k/g_v [B,H,T,DK]; MODE 3: row-major C.
// ---------------------------------------------------------------------------
template<int MODE>
__global__ __launch_bounds__(256)
void mma_gemm(const float* __restrict__ bias, float* __restrict__ C)
{
    extern __shared__ __nv_bfloat16 smem_raw[];
    const int tid = threadIdx.x;
    const int lane = tid & 31;
    const int warp = tid >> 5;
    const int wm = warp >> 1;          // 0..3
    const int wn = warp & 1;           // 0..1
    const int bm = blockIdx.y * 128;
    const int bn = blockIdx.x * 128;

    const __nv_bfloat16* Ah = g_hi + (MODE == 3 ? AOFF : XOFF);
    const __nv_bfloat16* Al = g_lo + (MODE == 3 ? AOFF : XOFF);
    const __nv_bfloat16* Wh = g_hi + WOFF + (size_t)MODE * N_ * K_;
    const __nv_bfloat16* Wl = g_lo + WOFF + (size_t)MODE * N_ * K_;

    uint32_t sbase = (uint32_t)__cvta_generic_to_shared(smem_raw);

    float acc[2][8][4];
#pragma unroll
    for (int mi = 0; mi < 2; ++mi)
#pragma unroll
        for (int ni = 0; ni < 8; ++ni)
#pragma unroll
            for (int r = 0; r < 4; ++r) acc[mi][ni][r] = 0.0f;

    constexpr int NT = K_ / 32;   // 32 k-chunks

    stage_load(Ah, Al, Wh, Wl, sbase, bm, bn, 0, tid);

#pragma unroll 1
    for (int kt = 0; kt < NT; ++kt) {
        const int s = kt & 1;
        if (kt + 1 < NT) {
            stage_load(Ah, Al, Wh, Wl, sbase + (s ^ 1) * STAGE_B, bm, bn, (kt + 1) * 32, tid);
            asm volatile("cp.async.wait_group 1;\n" ::);
        } else {
            asm volatile("cp.async.wait_group 0;\n" ::);
        }
        __syncthreads();

        const uint32_t sb = sbase + s * STAGE_B;
#pragma unroll
        for (int k16 = 0; k16 < 2; ++k16) {
            uint32_t ah[2][4], al[2][4];
#pragma unroll
            for (int mi = 0; mi < 2; ++mi) {
                int row = wm * 32 + mi * 16 + (lane & 15);
                uint32_t off = (uint32_t)(row * 80 + ((lane >> 4) * 8 + k16 * 16) * 2);
                ldsm4(ah[mi], sb + off);
                ldsm4(al[mi], sb + 10240 + off);
            }
#pragma unroll
            for (int nq = 0; nq < 4; ++nq) {
                int wrow = wn * 64 + nq * 16 + (lane & 7) + ((lane >> 4) << 3);
                uint32_t off = (uint32_t)(wrow * 80 + (((lane >> 3) & 1) * 8 + k16 * 16) * 2);
                uint32_t bh[4], bl[4];
                ldsm4(bh, sb + 20480 + off);
                ldsm4(bl, sb + 30720 + off);
#pragma unroll
                for (int mi = 0; mi < 2; ++mi) {
                    mma16816(acc[mi][nq * 2],     ah[mi], bh);
                    mma16816(acc[mi][nq * 2],     ah[mi], bl);
                    mma16816(acc[mi][nq * 2],     al[mi], bh);
                    mma16816(acc[mi][nq * 2 + 1], ah[mi], bh + 2);
                    mma16816(acc[mi][nq * 2 + 1], ah[mi], bl + 2);
                    mma16816(acc[mi][nq * 2 + 1], al[mi], bh + 2);
                }
            }
        }
        __syncthreads();
    }

    // Epilogue: add bias, write out
#pragma unroll
    for (int mi = 0; mi < 2; ++mi) {
#pragma unroll
        for (int ni = 0; ni < 8; ++ni) {
            const int r0 = bm + wm * 32 + mi * 16 + (lane >> 2);
            const int c0 = bn + wn * 64 + ni * 8 + (lane & 3) * 2;
            const float b0 = bias[c0];
            const float b1 = bias[c0 + 1];
            float2 v01 = make_float2(acc[mi][ni][0] + b0, acc[mi][ni][1] + b1);
            float2 v23 = make_float2(acc[mi][ni][2] + b0, acc[mi][ni][3] + b1);
            if (MODE == 3) {
                *(float2*)&C[(size_t)r0 * N_ + c0] = v01;
                *(float2*)&C[(size_t)(r0 + 8) * N_ + c0] = v23;
            } else {
                float* dst = (MODE == 0) ? g_q : (MODE == 1) ? g_k : g_v;
                const int h = c0 >> 6;
                const int d = c0 & (DK_ - 1);
                {
                    const int b = r0 >> 11, t = r0 & (T_ - 1);
                    *(float2*)&dst[(((size_t)b * H_ + h) * T_ + t) * DK_ + d] = v01;
                }
                {
                    const int r1 = r0 + 8;
                    const int b = r1 >> 11, t = r1 & (T_ - 1);
                    *(float2*)&dst[(((size_t)b * H_ + h) * T_ + t) * DK_ + d] = v23;
                }
            }
        }
    }
}

// ---------------------------------------------------------------------------
// Flash attention, fp32, causal (unchanged from R0).
// ---------------------------------------------------------------------------
__global__ __launch_bounds__(256, 1)
void attn_kernel()
{
    extern __shared__ float sm[];
    float* Qs = sm;                          // 64*64
    float* KPs = Qs + 64 * 64;               // 64*68 (K tile, then P tile)
    float* Vs = KPs + 64 * 68;               // 64*64
    float* row_m = Vs + 64 * 64;              // 64
    float* row_l = row_m + 64;                // 64
    float* row_scale = row_l + 64;            // 64

    const int tid = threadIdx.x;
    const int tx = tid & 15;
    const int ty = tid >> 4;
    const int i0 = ty * 4;
    const int j0 = tx * 4;

    const int bh = blockIdx.y;      // 0..63
    const int qt = blockIdx.x;      // 0..31 (query tile)

    const float* Qg = g_q + (size_t)bh * T_ * DK_ + (size_t)qt * 64 * DK_;
    const float* Kg0 = g_k + (size_t)bh * T_ * DK_;
    const float* Vg0 = g_v + (size_t)bh * T_ * DK_;

#pragma unroll
    for (int it = 0; it < 4; ++it) {
        const int idx = tid + it * 256;
        const int r = idx >> 4;
        const int c = (idx & 15) * 4;
        *(float4*)&Qs[r * 64 + c] = *(const float4*)(Qg + r * 64 + c);
    }
    if (tid < 64) { row_m[tid] = -1e30f; row_l[tid] = 0.0f; }

    float o[4][4];
#pragma unroll
    for (int i = 0; i < 4; ++i)
#pragma unroll
        for (int j = 0; j < 4; ++j) o[i][j] = 0.0f;

    __syncthreads();

    const float invs = 0.125f;   // 1/sqrt(64)

    for (int kt = 0; kt <= qt; ++kt) {
        const float* Kg = Kg0 + (size_t)kt * 64 * DK_;
        const float* Vg = Vg0 + (size_t)kt * 64 * DK_;
#pragma unroll
        for (int it = 0; it < 4; ++it) {
            const int idx = tid + it * 256;
            const int r = idx >> 4;
            const int c = (idx & 15) * 4;
            *(float4*)&KPs[r * 68 + c] = *(const float4*)(Kg + r * 64 + c);
            *(float4*)&Vs[r * 64 + c] = *(const float4*)(Vg + r * 64 + c);
        }
        __syncthreads();

        float s[4][4];
#pragma unroll
        for (int i = 0; i < 4; ++i)
#pragma unroll
            for (int j = 0; j < 4; ++j) s[i][j] = 0.0f;

        for (int d = 0; d < 64; d += 4) {
            float qv[4][4], kv[4][4];
#pragma unroll
            for (int i = 0; i < 4; ++i) {
                float4 t4 = *(const float4*)&Qs[(i0 + i) * 64 + d];
                qv[i][0] = t4.x; qv[i][1] = t4.y; qv[i][2] = t4.z; qv[i][3] = t4.w;
            }
#pragma unroll
            for (int j = 0; j < 4; ++j) {
                float4 t4 = *(const float4*)&KPs[(j0 + j) * 68 + d];
                kv[j][0] = t4.x; kv[j][1] = t4.y; kv[j][2] = t4.z; kv[j][3] = t4.w;
            }
#pragma unroll
            for (int i = 0; i < 4; ++i)
#pragma unroll
                for (int j = 0; j < 4; ++j)
#pragma unroll
                    for (int c = 0; c < 4; ++c)
                        s[i][j] = fmaf(qv[i][c], kv[j][c], s[i][j]);
        }

        if (kt == qt) {
#pragma unroll
            for (int i = 0; i < 4; ++i)
#pragma unroll
                for (int j = 0; j < 4; ++j)
                    s[i][j] = ((j0 + j) <= (i0 + i)) ? s[i][j] * invs : -1e30f;
        } else {
#pragma unroll
            for (int i = 0; i < 4; ++i)
#pragma unroll
                for (int j = 0; j < 4; ++j) s[i][j] *= invs;
        }

        __syncthreads();

#pragma unroll
        for (int i = 0; i < 4; ++i)
#pragma unroll
            for (int j = 0; j < 4; ++j)
                KPs[(i0 + i) * 68 + (j0 + j)] = s[i][j];
        __syncthreads();

        if (tid < 64) {
            float* pr = &KPs[tid * 68];
            const float mo = row_m[tid];
            float mt = mo;
#pragma unroll 8
            for (int j = 0; j < 64; ++j) mt = fmaxf(mt, pr[j]);
            const float sc = __expf(mo - mt);
            float l = row_l[tid] * sc;
#pragma unroll 8
            for (int j = 0; j < 64; ++j) {
                const float p = __expf(pr[j] - mt);
                pr[j] = p;
                l += p;
            }
            row_m[tid] = mt;
            row_l[tid] = l;
            row_scale[tid] = sc;
        }
        __syncthreads();

        float fac[4];
#pragma unroll
        for (int i = 0; i < 4; ++i) fac[i] = row_scale[i0 + i];
#pragma unroll
        for (int i = 0; i < 4; ++i)
#pragma unroll
            for (int j = 0; j < 4; ++j) o[i][j] *= fac[i];

        for (int k = 0; k < 64; k += 4) {
            float pv[4][4], vv[4][4];
#pragma unroll
            for (int i = 0; i < 4; ++i) {
                float4 t4 = *(const float4*)&KPs[(i0 + i) * 68 + k];
                pv[i][0] = t4.x; pv[i][1] = t4.y; pv[i][2] = t4.z; pv[i][3] = t4.w;
            }
#pragma unroll
            for (int c = 0; c < 4; ++c) {
                float4 t4 = *(const float4*)&Vs[(k + c) * 64 + j0];
                vv[c][0] = t4.x; vv[c][1] = t4.y; vv[c][2] = t4.z; vv[c][3] = t4.w;
            }
#pragma unroll
            for (int i = 0; i < 4; ++i)
#pragma unroll
                for (int j = 0; j < 4; ++j)
#pragma unroll
                    for (int c = 0; c < 4; ++c)
                        o[i][j] = fmaf(pv[i][c], vv[c][j], o[i][j]);
        }
        __syncthreads();
    }

    const int b = bh >> 4;
    const int h = bh & 15;
#pragma unroll
    for (int i = 0; i < 4; ++i) {
        const float inv = 1.0f / row_l[i0 + i];
        const int t = qt * 64 + i0 + i;
        float* outp = g_attn + ((size_t)b * T_ + t) * D_ + h * DK_ + j0;
#pragma unroll
        for (int j = 0; j < 4; ++j) outp[j] = o[i][j] * inv;
    }
}

// ---------------------------------------------------------------------------
// Launch
// ---------------------------------------------------------------------------
extern "C" void kernel_launch(void* const* d_in, const int* in_sizes, int n_in,
                              void* d_out, int out_size)
{
    (void)in_sizes; (void)n_in; (void)out_size;
    const float* x  = (const float*)d_in[0];
    const float* Wq = (const float*)d_in[2];
    const float* Wk = (const float*)d_in[3];
    const float* Wv = (const float*)d_in[4];
    const float* Wo = (const float*)d_in[5];
    const float* bq = (const float*)d_in[6];
    const float* bk = (const float*)d_in[7];
    const float* bv = (const float*)d_in[8];
    const float* bo = (const float*)d_in[9];
    float* out = (float*)d_out;

    // bf16 hi/lo splits
    const int n4x = M_ * K_ / 4;   // 2097152
    const int n4w = N_ * K_ / 4;   // 262144
    split_kernel<<<n4x / 256, 256>>>(x,  XOFF, n4x);
    split_kernel<<<n4w / 256, 256>>>(Wq, WOFF + 0ull * N_ * K_, n4w);
    split_kernel<<<n4w / 256, 256>>>(Wk, WOFF + 1ull * N_ * K_, n4w);
    split_kernel<<<n4w / 256, 256>>>(Wv, WOFF + 2ull * N_ * K_, n4w);
    split_kernel<<<n4w / 256, 256>>>(Wo, WOFF + 3ull * N_ * K_, n4w);

    const int gemm_smem = 2 * STAGE_B;  // 81920
    cudaFuncSetAttribute(mma_gemm<0>, cudaFuncAttributeMaxDynamicSharedMemorySize, gemm_smem);
    cudaFuncSetAttribute(mma_gemm<1>, cudaFuncAttributeMaxDynamicSharedMemorySize, gemm_smem);
    cudaFuncSetAttribute(mma_gemm<2>, cudaFuncAttributeMaxDynamicSharedMemorySize, gemm_smem);
    cudaFuncSetAttribute(mma_gemm<3>, cudaFuncAttributeMaxDynamicSharedMemorySize, gemm_smem);

    dim3 ggrid(N_ / 128, M_ / 128);   // (8, 64)
    mma_gemm<0><<<ggrid, 256, gemm_smem>>>(bq, nullptr);
    mma_gemm<1><<<ggrid, 256, gemm_smem>>>(bk, nullptr);
    mma_gemm<2><<<ggrid, 256, gemm_smem>>>(bv, nullptr);

    const int attn_smem = (64 * 64 + 64 * 68 + 64 * 64 + 3 * 64) * (int)sizeof(float);
    cudaFuncSetAttribute(attn_kernel, cudaFuncAttributeMaxDynamicSharedMemorySize, attn_smem);
    attn_kernel<<<dim3(T_ / 64, B_ * H_), 256, attn_smem>>>();

    // split attention output for the final projection
    float* pattn = nullptr;
    cudaGetSymbolAddress((void**)&pattn, g_attn);
    split_kernel<<<n4x / 256, 256>>>(pattn, AOFF, n4x);

    mma_gemm<3><<<ggrid, 256, gemm_smem>>>(bo, out);
}

// round 3
// speedup vs baseline: 3.3015x; 2.2163x over previous
#include <cuda_runtime.h>
#include <cuda_bf16.h>
#include <math.h>
#include <stdint.h>

// Problem constants
constexpr int B_ = 4;
constexpr int T_ = 2048;
constexpr int D_ = 1024;
constexpr int H_ = 16;
constexpr int DK_ = 64;
constexpr int M_ = B_ * T_;   // 8192
constexpr int N_ = D_;        // 1024
constexpr int K_ = D_;        // 1024

// bf16 split arenas (hi + lo). Layout: [x (M*K)][W0..W3 (4*N*K)][attn-out (M*D)]
constexpr size_t XOFF = 0;
constexpr size_t WOFF = (size_t)M_ * K_;
constexpr size_t AOFF = WOFF + 4ull * N_ * K_;
constexpr size_t ARENA = AOFF + (size_t)M_ * D_;

__device__ __nv_bfloat16 g_hi[ARENA];
__device__ __nv_bfloat16 g_lo[ARENA];

// Q/K/V in bf16 hi/lo, layout [B*H, T, DK]
constexpr size_t QKV_SZ = (size_t)B_ * H_ * T_ * DK_;
__device__ __nv_bfloat16 g_qh[QKV_SZ], g_ql[QKV_SZ];
__device__ __nv_bfloat16 g_kh[QKV_SZ], g_kl[QKV_SZ];
__device__ __nv_bfloat16 g_vh[QKV_SZ], g_vl[QKV_SZ];

// ---------------------------------------------------------------------------
// Split fp32 -> bf16 hi + bf16 lo
// ---------------------------------------------------------------------------
__global__ void split_kernel(const float* __restrict__ in, size_t dstOff, int n4)
{
    int i = blockIdx.x * blockDim.x + threadIdx.x;
    if (i >= n4) return;
    float4 v = ((const float4*)in)[i];
    float vv[4] = {v.x, v.y, v.z, v.w};
    __nv_bfloat16 h[4], l[4];
#pragma unroll
    for (int c = 0; c < 4; ++c) {
        h[c] = __float2bfloat16_rn(vv[c]);
        l[c] = __float2bfloat16_rn(vv[c] - __bfloat162float(h[c]));
    }
    __nv_bfloat162* ph = (__nv_bfloat162*)(g_hi + dstOff + (size_t)i * 4);
    __nv_bfloat162* pl = (__nv_bfloat162*)(g_lo + dstOff + (size_t)i * 4);
    ph[0] = __halves2bfloat162(h[0], h[1]);
    ph[1] = __halves2bfloat162(h[2], h[3]);
    pl[0] = __halves2bfloat162(l[0], l[1]);
    pl[1] = __halves2bfloat162(l[2], l[3]);
}

// ---------------------------------------------------------------------------
// MMA helpers
// ---------------------------------------------------------------------------
__device__ __forceinline__ void cp16(uint32_t dst, const void* src)
{
    asm volatile("cp.async.cg.shared.global [%0],[%1],16;\n" :: "r"(dst), "l"(src));
}
__device__ __forceinline__ void ldsm4(uint32_t* r, uint32_t addr)
{
    asm volatile("ldmatrix.sync.aligned.m8n8.x4.shared.b16 {%0,%1,%2,%3},[%4];"
                 : "=r"(r[0]), "=r"(r[1]), "=r"(r[2]), "=r"(r[3]) : "r"(addr));
}
__device__ __forceinline__ void ldsm4t(uint32_t* r, uint32_t addr)
{
    asm volatile("ldmatrix.sync.aligned.m8n8.x4.trans.shared.b16 {%0,%1,%2,%3},[%4];"
                 : "=r"(r[0]), "=r"(r[1]), "=r"(r[2]), "=r"(r[3]) : "r"(addr));
}
__device__ __forceinline__ void mma16816(float* c, const uint32_t* a, const uint32_t* b)
{
    asm volatile(
        "mma.sync.aligned.m16n8k16.row.col.f32.bf16.bf16.f32 "
        "{%0,%1,%2,%3},{%4,%5,%6,%7},{%8,%9},{%0,%1,%2,%3};"
        : "+f"(c[0]), "+f"(c[1]), "+f"(c[2]), "+f"(c[3])
        : "r"(a[0]), "r"(a[1]), "r"(a[2]), "r"(a[3]), "r"(b[0]), "r"(b[1]));
}

// Fast exp: degree-5 poly for 2^f + exponent splice. x <= 0 expected.
__device__ __forceinline__ float fexp(float x)
{
    float t = fmaxf(x * 1.4426950408889634f, -126.0f);
    int n = __float2int_rn(t);
    float f = t - (float)n;
    float p = 1.33336621e-3f;
    p = fmaf(p, f, 9.61812910e-3f);
    p = fmaf(p, f, 5.55041087e-2f);
    p = fmaf(p, f, 2.40226507e-1f);
    p = fmaf(p, f, 6.93147182e-1f);
    p = fmaf(p, f, 1.0f);
    return __int_as_float(__float_as_int(p) + (n << 23));
}

// ---------------------------------------------------------------------------
// Tensor-core GEMM: C = A @ W^T + bias, error-compensated bf16 (3 MMAs).
// MODE 0/1/2: write bf16 hi/lo into g_{q,k,v}{h,l} with [B*H,T,DK] layout.
// MODE 3:     write fp32 row-major C (d_out).
// 128x128 block, BK=32, 8 warps (4m x 2n), warp tile 32x64.
// ---------------------------------------------------------------------------
constexpr int STAGE_B = 40960;

__device__ __forceinline__ void stage_load(
    const __nv_bfloat16* Ah, const __nv_bfloat16* Al,
    const __nv_bfloat16* Wh, const __nv_bfloat16* Wl,
    uint32_t sb, int bm, int bn, int k0, int tid)
{
#pragma unroll
    for (int half = 0; half < 2; ++half) {
        int c = tid + half * 256;
        int row = c >> 2;
        int cc = c & 3;
        uint32_t so = (uint32_t)(row * 80 + cc * 16);
        size_t ga = (size_t)(bm + row) * K_ + k0 + cc * 8;
        size_t gw = (size_t)(bn + row) * K_ + k0 + cc * 8;
        cp16(sb + so,         Ah + ga);
        cp16(sb + 10240 + so, Al + ga);
        cp16(sb + 20480 + so, Wh + gw);
        cp16(sb + 30720 + so, Wl + gw);
    }
    asm volatile("cp.async.commit_group;\n" ::);
}

template<int MODE>
__global__ __launch_bounds__(256)
void mma_gemm(const float* __restrict__ bias, float* __restrict__ C)
{
    extern __shared__ __nv_bfloat16 smem_raw[];
    const int tid = threadIdx.x;
    const int lane = tid & 31;
    const int warp = tid >> 5;
    const int wm = warp >> 1;
    const int wn = warp & 1;
    const int bm = blockIdx.y * 128;
    const int bn = blockIdx.x * 128;

    const __nv_bfloat16* Ah = g_hi + (MODE == 3 ? AOFF : XOFF);
    const __nv_bfloat16* Al = g_lo + (MODE == 3 ? AOFF : XOFF);
    const __nv_bfloat16* Wh = g_hi + WOFF + (size_t)MODE * N_ * K_;
    const __nv_bfloat16* Wl = g_lo + WOFF + (size_t)MODE * N_ * K_;

    uint32_t sbase = (uint32_t)__cvta_generic_to_shared(smem_raw);

    float acc[2][8][4];
#pragma unroll
    for (int mi = 0; mi < 2; ++mi)
#pragma unroll
        for (int ni = 0; ni < 8; ++ni)
#pragma unroll
            for (int r = 0; r < 4; ++r) acc[mi][ni][r] = 0.0f;

    constexpr int NT = K_ / 32;

    stage_load(Ah, Al, Wh, Wl, sbase, bm, bn, 0, tid);

#pragma unroll 1
    for (int kt = 0; kt < NT; ++kt) {
        const int s = kt & 1;
        if (kt + 1 < NT) {
            stage_load(Ah, Al, Wh, Wl, sbase + (s ^ 1) * STAGE_B, bm, bn, (kt + 1) * 32, tid);
            asm volatile("cp.async.wait_group 1;\n" ::);
        } else {
            asm volatile("cp.async.wait_group 0;\n" ::);
        }
        __syncthreads();

        const uint32_t sb = sbase + s * STAGE_B;
#pragma unroll
        for (int k16 = 0; k16 < 2; ++k16) {
            uint32_t ah[2][4], al[2][4];
#pragma unroll
            for (int mi = 0; mi < 2; ++mi) {
                int row = wm * 32 + mi * 16 + (lane & 15);
                uint32_t off = (uint32_t)(row * 80 + ((lane >> 4) * 8 + k16 * 16) * 2);
                ldsm4(ah[mi], sb + off);
                ldsm4(al[mi], sb + 10240 + off);
            }
#pragma unroll
            for (int nq = 0; nq < 4; ++nq) {
                int wrow = wn * 64 + nq * 16 + (lane & 7) + ((lane >> 4) << 3);
                uint32_t off = (uint32_t)(wrow * 80 + (((lane >> 3) & 1) * 8 + k16 * 16) * 2);
                uint32_t bh[4], bl[4];
                ldsm4(bh, sb + 20480 + off);
                ldsm4(bl, sb + 30720 + off);
#pragma unroll
                for (int mi = 0; mi < 2; ++mi) {
                    mma16816(acc[mi][nq * 2],     ah[mi], bh);
                    mma16816(acc[mi][nq * 2],     ah[mi], bl);
                    mma16816(acc[mi][nq * 2],     al[mi], bh);
                    mma16816(acc[mi][nq * 2 + 1], ah[mi], bh + 2);
                    mma16816(acc[mi][nq * 2 + 1], ah[mi], bl + 2);
                    mma16816(acc[mi][nq * 2 + 1], al[mi], bh + 2);
                }
            }
        }
        __syncthreads();
    }

#pragma unroll
    for (int mi = 0; mi < 2; ++mi) {
#pragma unroll
        for (int ni = 0; ni < 8; ++ni) {
            const int r0 = bm + wm * 32 + mi * 16 + (lane >> 2);
            const int c0 = bn + wn * 64 + ni * 8 + (lane & 3) * 2;
            const float b0 = bias[c0];
            const float b1 = bias[c0 + 1];
            float2 v01 = make_float2(acc[mi][ni][0] + b0, acc[mi][ni][1] + b1);
            float2 v23 = make_float2(acc[mi][ni][2] + b0, acc[mi][ni][3] + b1);
            if (MODE == 3) {
                *(float2*)&C[(size_t)r0 * N_ + c0] = v01;
                *(float2*)&C[(size_t)(r0 + 8) * N_ + c0] = v23;
            } else {
                __nv_bfloat16* dh = (MODE == 0) ? g_qh : (MODE == 1) ? g_kh : g_vh;
                __nv_bfloat16* dl = (MODE == 0) ? g_ql : (MODE == 1) ? g_kl : g_vl;
                const int h = c0 >> 6;
                const int d = c0 & (DK_ - 1);
#pragma unroll
                for (int rr = 0; rr < 2; ++rr) {
                    const int row = r0 + rr * 8;
                    const int b = row >> 11, t = row & (T_ - 1);
                    const float x0 = rr ? v23.x : v01.x;
                    const float x1 = rr ? v23.y : v01.y;
                    __nv_bfloat16 h0 = __float2bfloat16_rn(x0);
                    __nv_bfloat16 h1 = __float2bfloat16_rn(x1);
                    __nv_bfloat16 l0 = __float2bfloat16_rn(x0 - __bfloat162float(h0));
                    __nv_bfloat16 l1 = __float2bfloat16_rn(x1 - __bfloat162float(h1));
                    size_t off = (((size_t)b * H_ + h) * T_ + t) * DK_ + d;
                    *(__nv_bfloat162*)&dh[off] = __halves2bfloat162(h0, h1);
                    *(__nv_bfloat162*)&dl[off] = __halves2bfloat162(l0, l1);
                }
            }
        }
    }
}

// ---------------------------------------------------------------------------
// Flash attention v2: bf16 MMA with hi/lo compensation, causal.
// Block: 128 threads (4 warps), 64 query rows, 64-key tiles, DK=64.
// smem: Qh/Ql (64x72) + 2 stages of {Kh,Kl,Vh,Vl} (64x72 each).
// ---------------------------------------------------------------------------
constexpr int AT_STRIDE = 72;                         // padded smem row (bf16)
constexpr int AT_TILE = 64 * AT_STRIDE;               // 4608 elems
constexpr int AT_QBASE = 0;                           // Qh, Ql
constexpr int AT_KVBASE = 2 * AT_TILE;                // stages
constexpr int AT_STAGE = 4 * AT_TILE;                 // Kh,Kl,Vh,Vl
constexpr int AT_SMEM_ELEMS = AT_KVBASE + 2 * AT_STAGE;   // 46080
constexpr int AT_SMEM_BYTES = AT_SMEM_ELEMS * 2;          // 92160

__device__ __forceinline__ void at_load_kv(uint32_t sb, int stage, size_t gbase, int kt, int tid)
{
    const __nv_bfloat16* srcs[4] = {g_kh, g_kl, g_vh, g_vl};
    uint32_t stbase = sb + (AT_KVBASE + stage * AT_STAGE) * 2;
#pragma unroll
    for (int i = 0; i < 16; ++i) {
        const int idx = tid + i * 128;
        const int arr = i >> 2;                 // constant per i
        const int within = idx & 511;
        const int row = within >> 3;
        const int cc = within & 7;
        uint32_t so = stbase + (arr * AT_TILE + row * AT_STRIDE + cc * 8) * 2;
        cp16(so, srcs[arr] + gbase + (size_t)(kt * 64 + row) * DK_ + cc * 8);
    }
    asm volatile("cp.async.commit_group;\n" ::);
}

__global__ __launch_bounds__(128)
void attn_kernel()
{
    extern __shared__ __nv_bfloat16 at_sm[];
    uint32_t sb = (uint32_t)__cvta_generic_to_shared(at_sm);

    const int tid = threadIdx.x;
    const int lane = tid & 31;
    const int warp = tid >> 5;

    const int qt = (int)gridDim.x - 1 - (int)blockIdx.x;   // long blocks first
    const int bh = blockIdx.y;
    const size_t gbase = (size_t)bh * T_ * DK_;

    // Load Q tile (Qh, Ql)
    {
        const __nv_bfloat16* srcs[2] = {g_qh, g_ql};
#pragma unroll
        for (int i = 0; i < 8; ++i) {
            const int idx = tid + i * 128;
            const int arr = i >> 2;
            const int within = idx & 511;
            const int row = within >> 3;
            const int cc = within & 7;
            uint32_t so = sb + (arr * AT_TILE + row * AT_STRIDE + cc * 8) * 2;
            cp16(so, srcs[arr] + gbase + (size_t)(qt * 64 + row) * DK_ + cc * 8);
        }
    }
    at_load_kv(sb, 0, gbase, 0, tid);   // Q + first KV in group 0

    asm volatile("cp.async.wait_group 0;\n" ::);
    __syncthreads();

    // Hoist Q fragments (4 k16 chunks, hi & lo)
    uint32_t qh[4][4], ql[4][4];
#pragma unroll
    for (int k16 = 0; k16 < 4; ++k16) {
        int row = warp * 16 + (lane & 15);
        uint32_t off = (uint32_t)(row * AT_STRIDE + (lane >> 4) * 8 + k16 * 16) * 2;
        ldsm4(qh[k16], sb + off);
        ldsm4(ql[k16], sb + AT_TILE * 2 + off);
    }

    float oAcc[8][4];
#pragma unroll
    for (int nt = 0; nt < 8; ++nt)
#pragma unroll
        for (int c = 0; c < 4; ++c) oAcc[nt][c] = 0.0f;

    float m0 = -1e30f, m1 = -1e30f, l0 = 0.0f, l1 = 0.0f;

    const int row0g = qt * 64 + warp * 16 + (lane >> 2);

#pragma unroll 1
    for (int kt = 0; kt <= qt; ++kt) {
        const int s = kt & 1;
        if (kt + 1 <= qt) {
            at_load_kv(sb, s ^ 1, gbase, kt + 1, tid);
            asm volatile("cp.async.wait_group 1;\n" ::);
        } else {
            asm volatile("cp.async.wait_group 0;\n" ::);
        }
        __syncthreads();

        const uint32_t kvb = sb + (AT_KVBASE + s * AT_STAGE) * 2;

        // ---- S = Q @ K^T (hi/lo compensated) ----
        float sAcc[8][4];
#pragma unroll
        for (int nt = 0; nt < 8; ++nt)
#pragma unroll
            for (int c = 0; c < 4; ++c) sAcc[nt][c] = 0.0f;

#pragma unroll
        for (int k16 = 0; k16 < 4; ++k16) {
#pragma unroll
            for (int np = 0; np < 4; ++np) {
                int krow = np * 16 + (lane & 7) + ((lane >> 4) << 3);
                uint32_t off = (uint32_t)(krow * AT_STRIDE + ((lane >> 3) & 1) * 8 + k16 * 16) * 2;
                uint32_t kh[4], kl[4];
                ldsm4(kh, kvb + off);
                ldsm4(kl, kvb + AT_TILE * 2 + off);
                mma16816(sAcc[np * 2],     qh[k16], kh);
                mma16816(sAcc[np * 2],     qh[k16], kl);
                mma16816(sAcc[np * 2],     ql[k16], kh);
                mma16816(sAcc[np * 2 + 1], qh[k16], kh + 2);
                mma16816(sAcc[np * 2 + 1], qh[k16], kl + 2);
                mma16816(sAcc[np * 2 + 1], ql[k16], kh + 2);
            }
        }

        // ---- scale + causal mask ----
        const float invs = 0.125f;
        if (kt == qt) {
#pragma unroll
            for (int nt = 0; nt < 8; ++nt) {
                const int colb = kt * 64 + nt * 8 + (lane & 3) * 2;
#pragma unroll
                for (int c = 0; c < 4; ++c) {
                    const int col = colb + (c & 1);
                    const int row = row0g + ((c >> 1) << 3);
                    sAcc[nt][c] = (col <= row) ? sAcc[nt][c] * invs : -1e30f;
                }
            }
        } else {
#pragma unroll
            for (int nt = 0; nt < 8; ++nt)
#pragma unroll
                for (int c = 0; c < 4; ++c) sAcc[nt][c] *= invs;
        }

        // ---- online softmax (register, per 2 rows) ----
        float mx0 = -1e30f, mx1 = -1e30f;
#pragma unroll
        for (int nt = 0; nt < 8; ++nt) {
            mx0 = fmaxf(mx0, fmaxf(sAcc[nt][0], sAcc[nt][1]));
            mx1 = fmaxf(mx1, fmaxf(sAcc[nt][2], sAcc[nt][3]));
        }
        mx0 = fmaxf(mx0, __shfl_xor_sync(0xffffffffu, mx0, 1));
        mx0 = fmaxf(mx0, __shfl_xor_sync(0xffffffffu, mx0, 2));
        mx1 = fmaxf(mx1, __shfl_xor_sync(0xffffffffu, mx1, 1));
        mx1 = fmaxf(mx1, __shfl_xor_sync(0xffffffffu, mx1, 2));

        const float mn0 = fmaxf(m0, mx0);
        const float mn1 = fmaxf(m1, mx1);
        const float fac0 = fexp(m0 - mn0);
        const float fac1 = fexp(m1 - mn1);
        m0 = mn0; m1 = mn1;

        float sum0 = 0.0f, sum1 = 0.0f;
        uint32_t pah[8][2], pal[8][2];
#pragma unroll
        for (int nt = 0; nt < 8; ++nt) {
            float p0 = fexp(sAcc[nt][0] - m0);
            float p1 = fexp(sAcc[nt][1] - m0);
            float p2 = fexp(sAcc[nt][2] - m1);
            float p3 = fexp(sAcc[nt][3] - m1);
            sum0 += p0 + p1;
            sum1 += p2 + p3;
            __nv_bfloat16 h0 = __float2bfloat16_rn(p0), h1 = __float2bfloat16_rn(p1);
            __nv_bfloat16 h2 = __float2bfloat16_rn(p2), h3 = __float2bfloat16_rn(p3);
            __nv_bfloat162 hp01 = __halves2bfloat162(h0, h1);
            __nv_bfloat162 hp23 = __halves2bfloat162(h2, h3);
            pah[nt][0] = *(uint32_t*)&hp01;
            pah[nt][1] = *(uint32_t*)&hp23;
            __nv_bfloat162 lp01 = __halves2bfloat162(
                __float2bfloat16_rn(p0 - __bfloat162float(h0)),
                __float2bfloat16_rn(p1 - __bfloat162float(h1)));
            __nv_bfloat162 lp23 = __halves2bfloat162(
                __float2bfloat16_rn(p2 - __bfloat162float(h2)),
                __float2bfloat16_rn(p3 - __bfloat162float(h3)));
            pal[nt][0] = *(uint32_t*)&lp01;
            pal[nt][1] = *(uint32_t*)&lp23;
        }
        sum0 += __shfl_xor_sync(0xffffffffu, sum0, 1);
        sum0 += __shfl_xor_sync(0xffffffffu, sum0, 2);
        sum1 += __shfl_xor_sync(0xffffffffu, sum1, 1);
        sum1 += __shfl_xor_sync(0xffffffffu, sum1, 2);
        l0 = l0 * fac0 + sum0;
        l1 = l1 * fac1 + sum1;

#pragma unroll
        for (int nt = 0; nt < 8; ++nt) {
            oAcc[nt][0] *= fac0; oAcc[nt][1] *= fac0;
            oAcc[nt][2] *= fac1; oAcc[nt][3] *= fac1;
        }

        // ---- O += P @ V (hi/lo compensated) ----
        const uint32_t vb = kvb + 2 * AT_TILE * 2;   // Vh base
#pragma unroll
        for (int c16 = 0; c16 < 4; ++c16) {
            uint32_t pa_h[4] = {pah[2 * c16][0], pah[2 * c16][1],
                                pah[2 * c16 + 1][0], pah[2 * c16 + 1][1]};
            uint32_t pa_l[4] = {pal[2 * c16][0], pal[2 * c16][1],
                                pal[2 * c16 + 1][0], pal[2 * c16 + 1][1]};
#pragma unroll
            for (int np = 0; np < 4; ++np) {
                int vrow = c16 * 16 + (lane & 7) + 8 * ((lane >> 3) & 1);
                int vcol = np * 16 + 8 * (lane >> 4);
                uint32_t off = (uint32_t)(vrow * AT_STRIDE + vcol) * 2;
                uint32_t vh[4], vl[4];
                ldsm4t(vh, vb + off);
                ldsm4t(vl, vb + AT_TILE * 2 + off);
                mma16816(oAcc[np * 2],     pa_h, vh);
                mma16816(oAcc[np * 2],     pa_h, vl);
                mma16816(oAcc[np * 2],     pa_l, vh);
                mma16816(oAcc[np * 2 + 1], pa_h, vh + 2);
                mma16816(oAcc[np * 2 + 1], pa_h, vl + 2);
                mma16816(oAcc[np * 2 + 1], pa_l, vh + 2);
            }
        }
        __syncthreads();
    }

    // ---- epilogue: normalize, write hi/lo bf16 into final-GEMM arena ----
    const float inv0 = 1.0f / l0;
    const float inv1 = 1.0f / l1;
    const int b = bh >> 4;
    const int h = bh & 15;
#pragma unroll
    for (int rr = 0; rr < 2; ++rr) {
        const int t = qt * 64 + warp * 16 + (lane >> 2) + rr * 8;
        const float inv = rr ? inv1 : inv0;
        size_t rowoff = AOFF + ((size_t)b * T_ + t) * D_ + h * DK_ + (lane & 3) * 2;
#pragma unroll
        for (int nt = 0; nt < 8; ++nt) {
            const float x0 = oAcc[nt][rr * 2] * inv;
            const float x1 = oAcc[nt][rr * 2 + 1] * inv;
            __nv_bfloat16 h0 = __float2bfloat16_rn(x0);
            __nv_bfloat16 h1 = __float2bfloat16_rn(x1);
            __nv_bfloat16 lo0 = __float2bfloat16_rn(x0 - __bfloat162float(h0));
            __nv_bfloat16 lo1 = __float2bfloat16_rn(x1 - __bfloat162float(h1));
            *(__nv_bfloat162*)&g_hi[rowoff + nt * 8] = __halves2bfloat162(h0, h1);
            *(__nv_bfloat162*)&g_lo[rowoff + nt * 8] = __halves2bfloat162(lo0, lo1);
        }
    }
}

// ---------------------------------------------------------------------------
// Launch
// ---------------------------------------------------------------------------
extern "C" void kernel_launch(void* const* d_in, const int* in_sizes, int n_in,
                              void* d_out, int out_size)
{
    (void)in_sizes; (void)n_in; (void)out_size;
    const float* x  = (const float*)d_in[0];
    const float* Wq = (const float*)d_in[2];
    const float* Wk = (const float*)d_in[3];
    const float* Wv = (const float*)d_in[4];
    const float* Wo = (const float*)d_in[5];
    const float* bq = (const float*)d_in[6];
    const float* bk = (const float*)d_in[7];
    const float* bv = (const float*)d_in[8];
    const float* bo = (const float*)d_in[9];
    float* out = (float*)d_out;

    const int n4x = M_ * K_ / 4;
    const int n4w = N_ * K_ / 4;
    split_kernel<<<n4x / 256, 256>>>(x,  XOFF, n4x);
    split_kernel<<<n4w / 256, 256>>>(Wq, WOFF + 0ull * N_ * K_, n4w);
    split_kernel<<<n4w / 256, 256>>>(Wk, WOFF + 1ull * N_ * K_, n4w);
    split_kernel<<<n4w / 256, 256>>>(Wv, WOFF + 2ull * N_ * K_, n4w);
    split_kernel<<<n4w / 256, 256>>>(Wo, WOFF + 3ull * N_ * K_, n4w);

    const int gemm_smem = 2 * STAGE_B;
    cudaFuncSetAttribute(mma_gemm<0>, cudaFuncAttributeMaxDynamicSharedMemorySize, gemm_smem);
    cudaFuncSetAttribute(mma_gemm<1>, cudaFuncAttributeMaxDynamicSharedMemorySize, gemm_smem);
    cudaFuncSetAttribute(mma_gemm<2>, cudaFuncAttributeMaxDynamicSharedMemorySize, gemm_smem);
    cudaFuncSetAttribute(mma_gemm<3>, cudaFuncAttributeMaxDynamicSharedMemorySize, gemm_smem);
    cudaFuncSetAttribute(attn_kernel, cudaFuncAttributeMaxDynamicSharedMemorySize, AT_SMEM_BYTES);

    dim3 ggrid(N_ / 128, M_ / 128);
    mma_gemm<0><<<ggrid, 256, gemm_smem>>>(bq, nullptr);
    mma_gemm<1><<<ggrid, 256, gemm_smem>>>(bk, nullptr);
    mma_gemm<2><<<ggrid, 256, gemm_smem>>>(bv, nullptr);

    attn_kernel<<<dim3(T_ / 64, B_ * H_), 128, AT_SMEM_BYTES>>>();

    mma_gemm<3><<<ggrid, 256, gemm_smem>>>(bo, out);
}

// round 5
// speedup vs baseline: 3.7909x; 1.1483x over previous
#include <cuda_runtime.h>
#include <cuda_bf16.h>
#include <math.h>
#include <stdint.h>

// Problem constants
constexpr int B_ = 4;
constexpr int T_ = 2048;
constexpr int D_ = 1024;
constexpr int H_ = 16;
constexpr int DK_ = 64;
constexpr int M_ = B_ * T_;   // 8192
constexpr int N_ = D_;        // 1024
constexpr int K_ = D_;        // 1024

// bf16 split arenas (hi + lo). Layout: [x (M*K)][W0..W3 (4*N*K)][attn-out (M*D)]
constexpr size_t XOFF = 0;
constexpr size_t WOFF = (size_t)M_ * K_;
constexpr size_t AOFF = WOFF + 4ull * N_ * K_;
constexpr size_t ARENA = AOFF + (size_t)M_ * D_;

__device__ __nv_bfloat16 g_hi[ARENA];
__device__ __nv_bfloat16 g_lo[ARENA];

// Q/K/V in bf16 hi/lo, layout [B*H, T, DK]
constexpr size_t QKV_SZ = (size_t)B_ * H_ * T_ * DK_;
__device__ __nv_bfloat16 g_qh[QKV_SZ], g_ql[QKV_SZ];
__device__ __nv_bfloat16 g_kh[QKV_SZ], g_kl[QKV_SZ];
__device__ __nv_bfloat16 g_vh[QKV_SZ], g_vl[QKV_SZ];

// ---------------------------------------------------------------------------
// Split fp32 -> bf16 hi + bf16 lo
// ---------------------------------------------------------------------------
__global__ void split_kernel(const float* __restrict__ in, size_t dstOff, int n4)
{
    int i = blockIdx.x * blockDim.x + threadIdx.x;
    if (i >= n4) return;
    float4 v = ((const float4*)in)[i];
    float vv[4] = {v.x, v.y, v.z, v.w};
    __nv_bfloat16 h[4], l[4];
#pragma unroll
    for (int c = 0; c < 4; ++c) {
        h[c] = __float2bfloat16_rn(vv[c]);
        l[c] = __float2bfloat16_rn(vv[c] - __bfloat162float(h[c]));
    }
    __nv_bfloat162* ph = (__nv_bfloat162*)(g_hi + dstOff + (size_t)i * 4);
    __nv_bfloat162* pl = (__nv_bfloat162*)(g_lo + dstOff + (size_t)i * 4);
    ph[0] = __halves2bfloat162(h[0], h[1]);
    ph[1] = __halves2bfloat162(h[2], h[3]);
    pl[0] = __halves2bfloat162(l[0], l[1]);
    pl[1] = __halves2bfloat162(l[2], l[3]);
}

// ---------------------------------------------------------------------------
// MMA helpers
// ---------------------------------------------------------------------------
__device__ __forceinline__ void cp16(uint32_t dst, const void* src)
{
    asm volatile("cp.async.cg.shared.global [%0],[%1],16;\n" :: "r"(dst), "l"(src));
}
__device__ __forceinline__ void ldsm4(uint32_t* r, uint32_t addr)
{
    asm volatile("ldmatrix.sync.aligned.m8n8.x4.shared.b16 {%0,%1,%2,%3},[%4];"
                 : "=r"(r[0]), "=r"(r[1]), "=r"(r[2]), "=r"(r[3]) : "r"(addr));
}
__device__ __forceinline__ void ldsm4t(uint32_t* r, uint32_t addr)
{
    asm volatile("ldmatrix.sync.aligned.m8n8.x4.trans.shared.b16 {%0,%1,%2,%3},[%4];"
                 : "=r"(r[0]), "=r"(r[1]), "=r"(r[2]), "=r"(r[3]) : "r"(addr));
}
__device__ __forceinline__ void mma16816(float* c, const uint32_t* a, const uint32_t* b)
{
    asm volatile(
        "mma.sync.aligned.m16n8k16.row.col.f32.bf16.bf16.f32 "
        "{%0,%1,%2,%3},{%4,%5,%6,%7},{%8,%9},{%0,%1,%2,%3};"
        : "+f"(c[0]), "+f"(c[1]), "+f"(c[2]), "+f"(c[3])
        : "r"(a[0]), "r"(a[1]), "r"(a[2]), "r"(a[3]), "r"(b[0]), "r"(b[1]));
}

// Fast exp: degree-5 poly for 2^f + exponent splice. x <= 0 expected.
__device__ __forceinline__ float fexp(float x)
{
    float t = fmaxf(x * 1.4426950408889634f, -126.0f);
    int n = __float2int_rn(t);
    float f = t - (float)n;
    float p = 1.33336621e-3f;
    p = fmaf(p, f, 9.61812910e-3f);
    p = fmaf(p, f, 5.55041087e-2f);
    p = fmaf(p, f, 2.40226507e-1f);
    p = fmaf(p, f, 6.93147182e-1f);
    p = fmaf(p, f, 1.0f);
    return __int_as_float(__float_as_int(p) + (n << 23));
}

// ---------------------------------------------------------------------------
// Tensor-core GEMM: C = A @ W^T + bias, error-compensated bf16 (3 MMAs).
// QKV==1: fused Q/K/V projection — grid (24, 64), wsel = blockIdx.x>>3.
// QKV==0: output projection (A = attn arena, fp32 row-major C out).
// 128x128 block, BK=32, 8 warps (4m x 2n), 2 CTAs/SM.
// ---------------------------------------------------------------------------
constexpr int STAGE_B = 40960;

__device__ __forceinline__ void stage_load(
    const __nv_bfloat16* Ah, const __nv_bfloat16* Al,
    const __nv_bfloat16* Wh, const __nv_bfloat16* Wl,
    uint32_t sb, int bm, int bn, int k0, int tid)
{
#pragma unroll
    for (int half = 0; half < 2; ++half) {
        int c = tid + half * 256;
        int row = c >> 2;
        int cc = c & 3;
        uint32_t so = (uint32_t)(row * 80 + cc * 16);
        size_t ga = (size_t)(bm + row) * K_ + k0 + cc * 8;
        size_t gw = (size_t)(bn + row) * K_ + k0 + cc * 8;
        cp16(sb + so,         Ah + ga);
        cp16(sb + 10240 + so, Al + ga);
        cp16(sb + 20480 + so, Wh + gw);
        cp16(sb + 30720 + so, Wl + gw);
    }
    asm volatile("cp.async.commit_group;\n" ::);
}

template<int QKV>
__global__ __launch_bounds__(256, 2)
void mma_gemm(const float* __restrict__ b0p, const float* __restrict__ b1p,
              const float* __restrict__ b2p, float* __restrict__ C)
{
    extern __shared__ __nv_bfloat16 smem_raw[];
    const int tid = threadIdx.x;
    const int lane = tid & 31;
    const int warp = tid >> 5;
    const int wm = warp >> 1;
    const int wn = warp & 1;
    const int bm = blockIdx.y * 128;
    const int wsel = QKV ? (blockIdx.x >> 3) : 0;
    const int bn = (QKV ? (blockIdx.x & 7) : blockIdx.x) * 128;

    const __nv_bfloat16* Ah = g_hi + (QKV ? XOFF : AOFF);
    const __nv_bfloat16* Al = g_lo + (QKV ? XOFF : AOFF);
    const size_t woff = WOFF + (size_t)(QKV ? wsel : 3) * N_ * K_;
    const __nv_bfloat16* Wh = g_hi + woff;
    const __nv_bfloat16* Wl = g_lo + woff;
    const float* bias = QKV ? (wsel == 0 ? b0p : wsel == 1 ? b1p : b2p) : b0p;

    uint32_t sbase = (uint32_t)__cvta_generic_to_shared(smem_raw);

    float acc[2][8][4];
#pragma unroll
    for (int mi = 0; mi < 2; ++mi)
#pragma unroll
        for (int ni = 0; ni < 8; ++ni)
#pragma unroll
            for (int r = 0; r < 4; ++r) acc[mi][ni][r] = 0.0f;

    constexpr int NT = K_ / 32;

    stage_load(Ah, Al, Wh, Wl, sbase, bm, bn, 0, tid);

#pragma unroll 1
    for (int kt = 0; kt < NT; ++kt) {
        const int s = kt & 1;
        if (kt + 1 < NT) {
            stage_load(Ah, Al, Wh, Wl, sbase + (s ^ 1) * STAGE_B, bm, bn, (kt + 1) * 32, tid);
            asm volatile("cp.async.wait_group 1;\n" ::);
        } else {
            asm volatile("cp.async.wait_group 0;\n" ::);
        }
        __syncthreads();

        const uint32_t sb = sbase + s * STAGE_B;
#pragma unroll
        for (int k16 = 0; k16 < 2; ++k16) {
            uint32_t ah[2][4], al[2][4];
#pragma unroll
            for (int mi = 0; mi < 2; ++mi) {
                int row = wm * 32 + mi * 16 + (lane & 15);
                uint32_t off = (uint32_t)(row * 80 + ((lane >> 4) * 8 + k16 * 16) * 2);
                ldsm4(ah[mi], sb + off);
                ldsm4(al[mi], sb + 10240 + off);
            }
#pragma unroll
            for (int nq = 0; nq < 4; ++nq) {
                int wrow = wn * 64 + nq * 16 + (lane & 7) + ((lane >> 4) << 3);
                uint32_t off = (uint32_t)(wrow * 80 + (((lane >> 3) & 1) * 8 + k16 * 16) * 2);
                uint32_t bh[4], bl[4];
                ldsm4(bh, sb + 20480 + off);
                ldsm4(bl, sb + 30720 + off);
#pragma unroll
                for (int mi = 0; mi < 2; ++mi) {
                    mma16816(acc[mi][nq * 2],     ah[mi], bh);
                    mma16816(acc[mi][nq * 2],     ah[mi], bl);
                    mma16816(acc[mi][nq * 2],     al[mi], bh);
                    mma16816(acc[mi][nq * 2 + 1], ah[mi], bh + 2);
                    mma16816(acc[mi][nq * 2 + 1], ah[mi], bl + 2);
                    mma16816(acc[mi][nq * 2 + 1], al[mi], bh + 2);
                }
            }
        }
        __syncthreads();
    }

#pragma unroll
    for (int mi = 0; mi < 2; ++mi) {
#pragma unroll
        for (int ni = 0; ni < 8; ++ni) {
            const int r0 = bm + wm * 32 + mi * 16 + (lane >> 2);
            const int c0 = bn + wn * 64 + ni * 8 + (lane & 3) * 2;
            const float b0 = bias[c0];
            const float b1 = bias[c0 + 1];
            float2 v01 = make_float2(acc[mi][ni][0] + b0, acc[mi][ni][1] + b1);
            float2 v23 = make_float2(acc[mi][ni][2] + b0, acc[mi][ni][3] + b1);
            if (!QKV) {
                *(float2*)&C[(size_t)r0 * N_ + c0] = v01;
                *(float2*)&C[(size_t)(r0 + 8) * N_ + c0] = v23;
            } else {
                __nv_bfloat16* dh = (wsel == 0) ? g_qh : (wsel == 1) ? g_kh : g_vh;
                __nv_bfloat16* dl = (wsel == 0) ? g_ql : (wsel == 1) ? g_kl : g_vl;
                const int h = c0 >> 6;
                const int d = c0 & (DK_ - 1);
#pragma unroll
                for (int rr = 0; rr < 2; ++rr) {
                    const int row = r0 + rr * 8;
                    const int b = row >> 11, t = row & (T_ - 1);
                    const float x0 = rr ? v23.x : v01.x;
                    const float x1 = rr ? v23.y : v01.y;
                    __nv_bfloat16 h0 = __float2bfloat16_rn(x0);
                    __nv_bfloat16 h1 = __float2bfloat16_rn(x1);
                    __nv_bfloat16 l0 = __float2bfloat16_rn(x0 - __bfloat162float(h0));
                    __nv_bfloat16 l1 = __float2bfloat16_rn(x1 - __bfloat162float(h1));
                    size_t off = (((size_t)b * H_ + h) * T_ + t) * DK_ + d;
                    *(__nv_bfloat162*)&dh[off] = __halves2bfloat162(h0, h1);
                    *(__nv_bfloat162*)&dl[off] = __halves2bfloat162(l0, l1);
                }
            }
        }
    }
}

// ---------------------------------------------------------------------------
// Flash attention v2: bf16 MMA with hi/lo compensation, causal.
// Block: 128 threads (4 warps), 64 query rows, 64-key tiles, DK=64.
// ---------------------------------------------------------------------------
constexpr int AT_STRIDE = 72;
constexpr int AT_TILE = 64 * AT_STRIDE;
constexpr int AT_KVBASE = 2 * AT_TILE;
constexpr int AT_STAGE = 4 * AT_TILE;
constexpr int AT_SMEM_ELEMS = AT_KVBASE + 2 * AT_STAGE;
constexpr int AT_SMEM_BYTES = AT_SMEM_ELEMS * 2;   // 92160

__device__ __forceinline__ void at_load_kv(uint32_t sb, int stage, size_t gbase, int kt, int tid)
{
    const __nv_bfloat16* srcs[4] = {g_kh, g_kl, g_vh, g_vl};
    uint32_t stbase = sb + (AT_KVBASE + stage * AT_STAGE) * 2;
#pragma unroll
    for (int i = 0; i < 16; ++i) {
        const int idx = tid + i * 128;
        const int arr = i >> 2;
        const int within = idx & 511;
        const int row = within >> 3;
        const int cc = within & 7;
        uint32_t so = stbase + (arr * AT_TILE + row * AT_STRIDE + cc * 8) * 2;
        cp16(so, srcs[arr] + gbase + (size_t)(kt * 64 + row) * DK_ + cc * 8);
    }
    asm volatile("cp.async.commit_group;\n" ::);
}

__global__ __launch_bounds__(128, 2)
void attn_kernel()
{
    extern __shared__ __nv_bfloat16 at_sm[];
    uint32_t sb = (uint32_t)__cvta_generic_to_shared(at_sm);

    const int tid = threadIdx.x;
    const int lane = tid & 31;
    const int warp = tid >> 5;

    const int qt = (int)gridDim.x - 1 - (int)blockIdx.x;
    const int bh = blockIdx.y;
    const size_t gbase = (size_t)bh * T_ * DK_;

    {
        const __nv_bfloat16* srcs[2] = {g_qh, g_ql};
#pragma unroll
        for (int i = 0; i < 8; ++i) {
            const int idx = tid + i * 128;
            const int arr = i >> 2;
            const int within = idx & 511;
            const int row = within >> 3;
            const int cc = within & 7;
            uint32_t so = sb + (arr * AT_TILE + row * AT_STRIDE + cc * 8) * 2;
            cp16(so, srcs[arr] + gbase + (size_t)(qt * 64 + row) * DK_ + cc * 8);
        }
    }
    at_load_kv(sb, 0, gbase, 0, tid);

    asm volatile("cp.async.wait_group 0;\n" ::);
    __syncthreads();

    uint32_t qh[4][4], ql[4][4];
#pragma unroll
    for (int k16 = 0; k16 < 4; ++k16) {
        int row = warp * 16 + (lane & 15);
        uint32_t off = (uint32_t)(row * AT_STRIDE + (lane >> 4) * 8 + k16 * 16) * 2;
        ldsm4(qh[k16], sb + off);
        ldsm4(ql[k16], sb + AT_TILE * 2 + off);
    }

    float oAcc[8][4];
#pragma unroll
    for (int nt = 0; nt < 8; ++nt)
#pragma unroll
        for (int c = 0; c < 4; ++c) oAcc[nt][c] = 0.0f;

    float m0 = -1e30f, m1 = -1e30f, l0 = 0.0f, l1 = 0.0f;
    const int row0g = qt * 64 + warp * 16 + (lane >> 2);

#pragma unroll 1
    for (int kt = 0; kt <= qt; ++kt) {
        const int s = kt & 1;
        if (kt + 1 <= qt) {
            at_load_kv(sb, s ^ 1, gbase, kt + 1, tid);
            asm volatile("cp.async.wait_group 1;\n" ::);
        } else {
            asm volatile("cp.async.wait_group 0;\n" ::);
        }
        __syncthreads();

        const uint32_t kvb = sb + (AT_KVBASE + s * AT_STAGE) * 2;

        float sAcc[8][4];
#pragma unroll
        for (int nt = 0; nt < 8; ++nt)
#pragma unroll
            for (int c = 0; c < 4; ++c) sAcc[nt][c] = 0.0f;

#pragma unroll
        for (int k16 = 0; k16 < 4; ++k16) {
#pragma unroll
            for (int np = 0; np < 4; ++np) {
                int krow = np * 16 + (lane & 7) + ((lane >> 4) << 3);
                uint32_t off = (uint32_t)(krow * AT_STRIDE + ((lane >> 3) & 1) * 8 + k16 * 16) * 2;
                uint32_t kh[4], kl[4];
                ldsm4(kh, kvb + off);
                ldsm4(kl, kvb + AT_TILE * 2 + off);
                mma16816(sAcc[np * 2],     qh[k16], kh);
                mma16816(sAcc[np * 2],     qh[k16], kl);
                mma16816(sAcc[np * 2],     ql[k16], kh);
                mma16816(sAcc[np * 2 + 1], qh[k16], kh + 2);
                mma16816(sAcc[np * 2 + 1], qh[k16], kl + 2);
                mma16816(sAcc[np * 2 + 1], ql[k16], kh + 2);
            }
        }

        const float invs = 0.125f;
        if (kt == qt) {
#pragma unroll
            for (int nt = 0; nt < 8; ++nt) {
                const int colb = kt * 64 + nt * 8 + (lane & 3) * 2;
#pragma unroll
                for (int c = 0; c < 4; ++c) {
                    const int col = colb + (c & 1);
                    const int row = row0g + ((c >> 1) << 3);
                    sAcc[nt][c] = (col <= row) ? sAcc[nt][c] * invs : -1e30f;
                }
            }
        } else {
#pragma unroll
            for (int nt = 0; nt < 8; ++nt)
#pragma unroll
                for (int c = 0; c < 4; ++c) sAcc[nt][c] *= invs;
        }

        float mx0 = -1e30f, mx1 = -1e30f;
#pragma unroll
        for (int nt = 0; nt < 8; ++nt) {
            mx0 = fmaxf(mx0, fmaxf(sAcc[nt][0], sAcc[nt][1]));
            mx1 = fmaxf(mx1, fmaxf(sAcc[nt][2], sAcc[nt][3]));
        }
        mx0 = fmaxf(mx0, __shfl_xor_sync(0xffffffffu, mx0, 1));
        mx0 = fmaxf(mx0, __shfl_xor_sync(0xffffffffu, mx0, 2));
        mx1 = fmaxf(mx1, __shfl_xor_sync(0xffffffffu, mx1, 1));
        mx1 = fmaxf(mx1, __shfl_xor_sync(0xffffffffu, mx1, 2));

        const float mn0 = fmaxf(m0, mx0);
        const float mn1 = fmaxf(m1, mx1);
        const float fac0 = fexp(m0 - mn0);
        const float fac1 = fexp(m1 - mn1);
        m0 = mn0; m1 = mn1;

        float sum0 = 0.0f, sum1 = 0.0f;
        uint32_t pah[8][2], pal[8][2];
#pragma unroll
        for (int nt = 0; nt < 8; ++nt) {
            float p0 = fexp(sAcc[nt][0] - m0);
            float p1 = fexp(sAcc[nt][1] - m0);
            float p2 = fexp(sAcc[nt][2] - m1);
            float p3 = fexp(sAcc[nt][3] - m1);
            sum0 += p0 + p1;
            sum1 += p2 + p3;
            __nv_bfloat16 h0 = __float2bfloat16_rn(p0), h1 = __float2bfloat16_rn(p1);
            __nv_bfloat16 h2 = __float2bfloat16_rn(p2), h3 = __float2bfloat16_rn(p3);
            __nv_bfloat162 hp01 = __halves2bfloat162(h0, h1);
            __nv_bfloat162 hp23 = __halves2bfloat162(h2, h3);
            pah[nt][0] = *(uint32_t*)&hp01;
            pah[nt][1] = *(uint32_t*)&hp23;
            __nv_bfloat162 lp01 = __halves2bfloat162(
                __float2bfloat16_rn(p0 - __bfloat162float(h0)),
                __float2bfloat16_rn(p1 - __bfloat162float(h1)));
            __nv_bfloat162 lp23 = __halves2bfloat162(
                __float2bfloat16_rn(p2 - __bfloat162float(h2)),
                __float2bfloat16_rn(p3 - __bfloat162float(h3)));
            pal[nt][0] = *(uint32_t*)&lp01;
            pal[nt][1] = *(uint32_t*)&lp23;
        }
        sum0 += __shfl_xor_sync(0xffffffffu, sum0, 1);
        sum0 += __shfl_xor_sync(0xffffffffu, sum0, 2);
        sum1 += __shfl_xor_sync(0xffffffffu, sum1, 1);
        sum1 += __shfl_xor_sync(0xffffffffu, sum1, 2);
        l0 = l0 * fac0 + sum0;
        l1 = l1 * fac1 + sum1;

#pragma unroll
        for (int nt = 0; nt < 8; ++nt) {
            oAcc[nt][0] *= fac0; oAcc[nt][1] *= fac0;
            oAcc[nt][2] *= fac1; oAcc[nt][3] *= fac1;
        }

        const uint32_t vb = kvb + 2 * AT_TILE * 2;
#pragma unroll
        for (int c16 = 0; c16 < 4; ++c16) {
            uint32_t pa_h[4] = {pah[2 * c16][0], pah[2 * c16][1],
                                pah[2 * c16 + 1][0], pah[2 * c16 + 1][1]};
            uint32_t pa_l[4] = {pal[2 * c16][0], pal[2 * c16][1],
                                pal[2 * c16 + 1][0], pal[2 * c16 + 1][1]};
#pragma unroll
            for (int np = 0; np < 4; ++np) {
                int vrow = c16 * 16 + (lane & 7) + 8 * ((lane >> 3) & 1);
                int vcol = np * 16 + 8 * (lane >> 4);
                uint32_t off = (uint32_t)(vrow * AT_STRIDE + vcol) * 2;
                uint32_t vh[4], vl[4];
                ldsm4t(vh, vb + off);
                ldsm4t(vl, vb + AT_TILE * 2 + off);
                mma16816(oAcc[np * 2],     pa_h, vh);
                mma16816(oAcc[np * 2],     pa_h, vl);
                mma16816(oAcc[np * 2],     pa_l, vh);
                mma16816(oAcc[np * 2 + 1], pa_h, vh + 2);
                mma16816(oAcc[np * 2 + 1], pa_h, vl + 2);
                mma16816(oAcc[np * 2 + 1], pa_l, vh + 2);
            }
        }
        __syncthreads();
    }

    const float inv0 = 1.0f / l0;
    const float inv1 = 1.0f / l1;
    const int b = bh >> 4;
    const int h = bh & 15;
#pragma unroll
    for (int rr = 0; rr < 2; ++rr) {
        const int t = qt * 64 + warp * 16 + (lane >> 2) + rr * 8;
        const float inv = rr ? inv1 : inv0;
        size_t rowoff = AOFF + ((size_t)b * T_ + t) * D_ + h * DK_ + (lane & 3) * 2;
#pragma unroll
        for (int nt = 0; nt < 8; ++nt) {
            const float x0 = oAcc[nt][rr * 2] * inv;
            const float x1 = oAcc[nt][rr * 2 + 1] * inv;
            __nv_bfloat16 h0 = __float2bfloat16_rn(x0);
            __nv_bfloat16 h1 = __float2bfloat16_rn(x1);
            __nv_bfloat16 lo0 = __float2bfloat16_rn(x0 - __bfloat162float(h0));
            __nv_bfloat16 lo1 = __float2bfloat16_rn(x1 - __bfloat162float(h1));
            *(__nv_bfloat162*)&g_hi[rowoff + nt * 8] = __halves2bfloat162(h0, h1);
            *(__nv_bfloat162*)&g_lo[rowoff + nt * 8] = __halves2bfloat162(lo0, lo1);
        }
    }
}

// ---------------------------------------------------------------------------
// Launch
// ---------------------------------------------------------------------------
extern "C" void kernel_launch(void* const* d_in, const int* in_sizes, int n_in,
                              void* d_out, int out_size)
{
    (void)in_sizes; (void)n_in; (void)out_size;
    const float* x  = (const float*)d_in[0];
    const float* Wq = (const float*)d_in[2];
    const float* Wk = (const float*)d_in[3];
    const float* Wv = (const float*)d_in[4];
    const float* Wo = (const float*)d_in[5];
    const float* bq = (const float*)d_in[6];
    const float* bk = (const float*)d_in[7];
    const float* bv = (const float*)d_in[8];
    const float* bo = (const float*)d_in[9];
    float* out = (float*)d_out;

    const int n4x = M_ * K_ / 4;
    const int n4w = N_ * K_ / 4;
    split_kernel<<<n4x / 256, 256>>>(x,  XOFF, n4x);
    split_kernel<<<n4w / 256, 256>>>(Wq, WOFF + 0ull * N_ * K_, n4w);
    split_kernel<<<n4w / 256, 256>>>(Wk, WOFF + 1ull * N_ * K_, n4w);
    split_kernel<<<n4w / 256, 256>>>(Wv, WOFF + 2ull * N_ * K_, n4w);
    split_kernel<<<n4w / 256, 256>>>(Wo, WOFF + 3ull * N_ * K_, n4w);

    const int gemm_smem = 2 * STAGE_B;
    cudaFuncSetAttribute(mma_gemm<1>, cudaFuncAttributeMaxDynamicSharedMemorySize, gemm_smem);
    cudaFuncSetAttribute(mma_gemm<0>, cudaFuncAttributeMaxDynamicSharedMemorySize, gemm_smem);
    cudaFuncSetAttribute(attn_kernel, cudaFuncAttributeMaxDynamicSharedMemorySize, AT_SMEM_BYTES);

    // Fused QKV projection: grid (3*8, 64)
    mma_gemm<1><<<dim3(24, M_ / 128), 256, gemm_smem>>>(bq, bk, bv, nullptr);

    attn_kernel<<<dim3(T_ / 64, B_ * H_), 128, AT_SMEM_BYTES>>>();

    // Output projection
    mma_gemm<0><<<dim3(N_ / 128, M_ / 128), 256, gemm_smem>>>(bo, nullptr, nullptr, out);
}